// round 4
// baseline (speedup 1.0000x reference)
#include <cuda_runtime.h>
#include <cuda_bf16.h>

// src [8,16,512,512] f32, flow [8,2,512,512] f32, out [8,16,512,512] f32.
//
// Index math reproduces XLA's lowering bit-exactly (reciprocal-constant rewrite
// of /511, every intermediate fp32-rounded, no FMA contraction, rint half-to-even,
// border clamp). Verified rel_err == 0.0 in R3.
//
// Perf structure: 4 pixels per thread. Flow read as 2x LDG.128, output written
// as STG.128 per channel. Channel loop unrolled in groups of 4 with an explicit
// staging array so ptxas front-batches 16 gather LDGs (MLP ~16 vs ~3 at 32 regs).

#define B 8
#define C 16
#define H 512
#define W 512
#define HW (H * W)          // 1<<18
#define HW_BITS 18
#define W_BITS 9

__device__ __forceinline__ int ref_index(float coord, float disp)
{
    const float rcp = 1.0f / 511.0f;         // fp32(1/511), XLA recip rewrite
    float t = __fadd_rn(coord, disp);        // ii + flow
    t = __fmul_rn(t, rcp);                   // * (1/511)
    t = __fadd_rn(t, -0.5f);                 // - 0.5
    t = __fmul_rn(2.0f, t);                  // * 2 (exact)
    t = __fadd_rn(t, 1.0f);                  // + 1
    t = __fmul_rn(t, 0.5f);                  // * 0.5 (exact)
    t = __fmul_rn(t, 511.0f);                // * 511
    int i = __float2int_rn(t);               // round half-to-even
    return min(max(i, 0), 511);              // border clamp
}

__global__ __launch_bounds__(256, 4) void flow_warp_nearest_v4_kernel(
    const float* __restrict__ src,
    const float* __restrict__ flow,
    float* __restrict__ out)
{
    int t = blockIdx.x * blockDim.x + threadIdx.x;   // over B*HW/4
    int b   = t >> (HW_BITS - 2);
    int hw4 = (t & ((HW >> 2) - 1)) << 2;            // base pixel, multiple of 4
    int h   = hw4 >> W_BITS;
    int w   = hw4 & (W - 1);

    const float* fb = flow + (size_t)b * 2 * HW;
    float4 fy = __ldg((const float4*)(fb + hw4));        // row disp, 4 px
    float4 fx = __ldg((const float4*)(fb + HW + hw4));   // col disp, 4 px

    float hf = (float)h;
    int lin0 = (ref_index(hf, fy.x) << W_BITS) + ref_index((float)(w + 0), fx.x);
    int lin1 = (ref_index(hf, fy.y) << W_BITS) + ref_index((float)(w + 1), fx.y);
    int lin2 = (ref_index(hf, fy.z) << W_BITS) + ref_index((float)(w + 2), fx.z);
    int lin3 = (ref_index(hf, fy.w) << W_BITS) + ref_index((float)(w + 3), fx.w);

    const float* sb = src + (size_t)b * C * HW;
    float*       ob = out + (size_t)b * C * HW;

    #pragma unroll
    for (int c0 = 0; c0 < C; c0 += 4) {
        float4 v[4];
        #pragma unroll
        for (int j = 0; j < 4; ++j) {
            const float* s = sb + (c0 + j) * HW;
            v[j].x = __ldg(s + lin0);
            v[j].y = __ldg(s + lin1);
            v[j].z = __ldg(s + lin2);
            v[j].w = __ldg(s + lin3);
        }
        #pragma unroll
        for (int j = 0; j < 4; ++j) {
            *(float4*)(ob + (c0 + j) * HW + hw4) = v[j];
        }
    }
}

extern "C" void kernel_launch(void* const* d_in, const int* in_sizes, int n_in,
                              void* d_out, int out_size)
{
    const float* src  = (const float*)d_in[0];
    const float* flow = (const float*)d_in[1];
    float*       out  = (float*)d_out;

    int total = (B * HW) >> 2;          // 524,288 threads (4 px each)
    int threads = 256;
    int blocks = total / threads;       // 2048
    flow_warp_nearest_v4_kernel<<<blocks, threads>>>(src, flow, out);
}

// round 5
// speedup vs baseline: 1.0181x; 1.0181x over previous
#include <cuda_runtime.h>
#include <cuda_bf16.h>

// src [8,16,512,512] f32, flow [8,2,512,512] f32, out [8,16,512,512] f32.
//
// Index math reproduces XLA's lowering bit-exactly (reciprocal-constant rewrite
// of /511, every intermediate fp32-rounded, no FMA contraction, rint
// half-to-even, border clamp). Verified rel_err == 0.0 in R3/R4.
//
// Perf structure (R5): 2 pixels per thread — the occupancy x MLP sweet spot.
// launch_bounds(256,6) -> <=42 regs -> 48 warps/SM (75% occ), while the
// 4-channel staging group keeps 8 gather LDGs in flight per warp.

#define B 8
#define C 16
#define H 512
#define W 512
#define HW (H * W)          // 1<<18
#define HW_BITS 18
#define W_BITS 9

__device__ __forceinline__ int ref_index(float coord, float disp)
{
    const float rcp = 1.0f / 511.0f;         // fp32(1/511), XLA recip rewrite
    float t = __fadd_rn(coord, disp);        // ii + flow
    t = __fmul_rn(t, rcp);                   // * (1/511)
    t = __fadd_rn(t, -0.5f);                 // - 0.5
    t = __fmul_rn(2.0f, t);                  // * 2 (exact)
    t = __fadd_rn(t, 1.0f);                  // + 1
    t = __fmul_rn(t, 0.5f);                  // * 0.5 (exact)
    t = __fmul_rn(t, 511.0f);                // * 511
    int i = __float2int_rn(t);               // round half-to-even
    return min(max(i, 0), 511);              // border clamp
}

__global__ __launch_bounds__(256, 6) void flow_warp_nearest_v2_kernel(
    const float* __restrict__ src,
    const float* __restrict__ flow,
    float* __restrict__ out)
{
    int t = blockIdx.x * blockDim.x + threadIdx.x;   // over B*HW/2
    int b   = t >> (HW_BITS - 1);
    int hw2 = (t & ((HW >> 1) - 1)) << 1;            // base pixel, multiple of 2
    int h   = hw2 >> W_BITS;
    int w   = hw2 & (W - 1);

    const float* fb = flow + (size_t)b * 2 * HW;
    float2 fy = __ldg((const float2*)(fb + hw2));        // row disp, 2 px
    float2 fx = __ldg((const float2*)(fb + HW + hw2));   // col disp, 2 px

    float hf = (float)h;
    int lin0 = (ref_index(hf, fy.x) << W_BITS) + ref_index((float)(w + 0), fx.x);
    int lin1 = (ref_index(hf, fy.y) << W_BITS) + ref_index((float)(w + 1), fx.y);

    const float* sb = src + (size_t)b * C * HW;
    float*       ob = out + (size_t)b * C * HW;

    #pragma unroll
    for (int c0 = 0; c0 < C; c0 += 4) {
        float2 v[4];
        #pragma unroll
        for (int j = 0; j < 4; ++j) {
            const float* s = sb + (c0 + j) * HW;
            v[j].x = __ldg(s + lin0);        // 8 independent gathers in flight
            v[j].y = __ldg(s + lin1);
        }
        #pragma unroll
        for (int j = 0; j < 4; ++j) {
            *(float2*)(ob + (c0 + j) * HW + hw2) = v[j];
        }
    }
}

extern "C" void kernel_launch(void* const* d_in, const int* in_sizes, int n_in,
                              void* d_out, int out_size)
{
    const float* src  = (const float*)d_in[0];
    const float* flow = (const float*)d_in[1];
    float*       out  = (float*)d_out;

    int total = (B * HW) >> 1;          // 1,048,576 threads (2 px each)
    int threads = 256;
    int blocks = total / threads;       // 4096
    flow_warp_nearest_v2_kernel<<<blocks, threads>>>(src, flow, out);
}

// round 6
// speedup vs baseline: 1.0824x; 1.0632x over previous
#include <cuda_runtime.h>
#include <cuda_bf16.h>

// src [8,16,512,512] f32, flow [8,2,512,512] f32, out [8,16,512,512] f32.
//
// Index math reproduces XLA's lowering bit-exactly (reciprocal-constant rewrite
// of /511, every intermediate fp32-rounded, no FMA contraction, rint
// half-to-even, border clamp). Verified rel_err == 0.0 in R3/R4/R5.
//
// Perf structure (R6) = R3 (best: 1 px/thread, 32 regs, ~87% occ) plus cache
// policy control:
//   - output stores  -> __stcs  (evict-first; out is never re-read, don't let
//                                128MB of write-allocates thrash L2)
//   - flow loads     -> __ldcs  (streamed once)
//   - src gathers    -> __ldg   (default caching; L2/L1 reuse across
//                                vertically-neighboring warps is the win)

#define B 8
#define C 16
#define H 512
#define W 512
#define HW (H * W)          // 1<<18
#define HW_BITS 18
#define W_BITS 9

__device__ __forceinline__ int ref_index(float coord, float disp)
{
    const float rcp = 1.0f / 511.0f;         // fp32(1/511), XLA recip rewrite
    float t = __fadd_rn(coord, disp);        // ii + flow
    t = __fmul_rn(t, rcp);                   // * (1/511)
    t = __fadd_rn(t, -0.5f);                 // - 0.5
    t = __fmul_rn(2.0f, t);                  // * 2 (exact)
    t = __fadd_rn(t, 1.0f);                  // + 1
    t = __fmul_rn(t, 0.5f);                  // * 0.5 (exact)
    t = __fmul_rn(t, 511.0f);                // * 511
    int i = __float2int_rn(t);               // round half-to-even
    return min(max(i, 0), 511);              // border clamp
}

__global__ __launch_bounds__(256) void flow_warp_nearest_kernel(
    const float* __restrict__ src,
    const float* __restrict__ flow,
    float* __restrict__ out)
{
    int idx = blockIdx.x * blockDim.x + threadIdx.x;   // over B*H*W = 2M
    if (idx >= B * HW) return;

    int b  = idx >> HW_BITS;
    int hw = idx & (HW - 1);
    int h  = hw >> W_BITS;
    int w  = hw & (W - 1);

    const float* fb = flow + (size_t)b * 2 * HW;
    float f0 = __ldcs(fb + hw);          // row displacement (streaming)
    float f1 = __ldcs(fb + HW + hw);     // col displacement (streaming)

    int yi = ref_index((float)h, f0);
    int xi = ref_index((float)w, f1);
    int lin = (yi << W_BITS) + xi;

    const float* sb = src + (size_t)b * C * HW;
    float*       ob = out + (size_t)b * C * HW;

    #pragma unroll
    for (int c = 0; c < C; ++c) {
        __stcs(ob + c * HW + hw, __ldg(sb + c * HW + lin));
    }
}

extern "C" void kernel_launch(void* const* d_in, const int* in_sizes, int n_in,
                              void* d_out, int out_size)
{
    const float* src  = (const float*)d_in[0];
    const float* flow = (const float*)d_in[1];
    float*       out  = (float*)d_out;

    int total = B * HW;                 // 2,097,152 threads
    int threads = 256;
    int blocks = (total + threads - 1) / threads;   // 8192
    flow_warp_nearest_kernel<<<blocks, threads>>>(src, flow, out);
}